// round 7
// baseline (speedup 1.0000x reference)
#include <cuda_runtime.h>

#define NCOLS 32768
#define ROWS  8192
#define TPB   512
#define TPB2  256
#define F4PT  16            // K1: float4 per thread (16*4 = 64 floats)
#define KSEL  32
#define SCAP  1280          // per-row scratch capacity (mean 747, huge sigma margin)
#define EQCAP 128
#define FLOORV 2.0f

__device__ static uint2    g_cand[(size_t)ROWS * SCAP];   // (valbits, idx)
__device__ static unsigned g_cnt[ROWS];

__device__ __forceinline__ unsigned fkey(float f) {
    unsigned u = __float_as_uint(f);
    return u ^ ((u >> 31) ? 0xFFFFFFFFu : 0x80000000u);
}
__device__ __forceinline__ float keyf(unsigned k) {
    unsigned u = (k & 0x80000000u) ? (k ^ 0x80000000u) : ~k;
    return __uint_as_float(u);
}

// ===================== K1: pure streaming pass, no tail =====================
__global__ void __launch_bounds__(TPB)
k1_stream(const float* __restrict__ x, float* __restrict__ out) {
    const int row = blockIdx.x;
    const int t   = threadIdx.x;
    const float4* __restrict__ xin4 = (const float4*)(x + (size_t)row * NCOLS);
    float4* __restrict__ xo4 = (float4*)(out + (size_t)row * NCOLS);

    if (t == 0) g_cnt[row] = 0u;
    __syncthreads();                              // only barrier in K1

    uint2* __restrict__ clist = &g_cand[(size_t)row * SCAP];
    const float4 z4 = make_float4(0.f, 0.f, 0.f, 0.f);
#pragma unroll
    for (int jb = 0; jb < F4PT / 4; jb++) {
        float4 v[4];
#pragma unroll
        for (int u = 0; u < 4; u++)               // 4 back-to-back LDG.128
            v[u] = __ldcs(&xin4[t + (jb * 4 + u) * TPB]);
#pragma unroll
        for (int u = 0; u < 4; u++)               // 4 back-to-back STG.128
            __stcs(&xo4[t + (jb * 4 + u) * TPB], z4);
#pragma unroll
        for (int u = 0; u < 4; u++) {
            float m = fmaxf(fmaxf(v[u].x, v[u].y), fmaxf(v[u].z, v[u].w));
            if (m >= FLOORV) {                    // rare (~9% of threads/iter)
                const int base = (t + (jb * 4 + u) * TPB) * 4;
                const float* fp = (const float*)&v[u];
#pragma unroll
                for (int c = 0; c < 4; c++) {
                    float f = fp[c];
                    if (f >= FLOORV) {
                        unsigned pos = atomicAdd(&g_cnt[row], 1u);
                        if (pos < SCAP)
                            clist[pos] = make_uint2(__float_as_uint(f), (unsigned)(base + c));
                    }
                }
            }
        }
    }
}

// ===================== K2: selection over tiny candidate lists =====================
__global__ void __launch_bounds__(TPB2)
k2_select(const float* __restrict__ x, float* __restrict__ out) {
    __shared__ unsigned hist[256];
    __shared__ unsigned scn[257];                 // fallback only
    __shared__ int      flagS;
    __shared__ unsigned eq_cnt;
    __shared__ int      eq_idx[EQCAP];
    __shared__ unsigned eq_key[EQCAP];
    __shared__ unsigned sh_cut, sh_above;
    __shared__ unsigned sh_bin, sh_need, fb_eqc;
    __shared__ unsigned fb_list[SCAP];            // fallback eq indices

    const int row = blockIdx.x;
    const int t   = threadIdx.x;
    const float* __restrict__ xrow = x + (size_t)row * NCOLS;
    float* __restrict__ orow = out + (size_t)row * NCOLS;
    const uint2* __restrict__ clist = &g_cand[(size_t)row * SCAP];

    const unsigned cnt = g_cnt[row];
    if (t == 0) {
        flagS = (cnt < KSEL || cnt > SCAP) ? 1 : 0;
        eq_cnt = 0u;
    }
    hist[t] = 0u;                                 // TPB2 == 256
    __syncthreads();                              // [bar 1]

    // cache candidates in registers + histogram
    uint2 c[(SCAP + TPB2 - 1) / TPB2];            // <= 5 entries
    int myn = 0;
    if (!flagS) {
        for (int i = t; i < (int)cnt; i += TPB2) {
            uint2 e = clist[i];                   // coalesced 8B
            c[myn++] = e;
            unsigned bin = (e.x >> 16) - 0x4000u;
            bin = (bin > 255u) ? 255u : bin;
            atomicAdd(&hist[bin], 1u);
        }
    }
    __syncthreads();                              // [bar 2]

    // warp-0 suffix scan over 256 bins
    if (t < 32) {
        unsigned h[8], tot = 0u;
#pragma unroll
        for (int q = 0; q < 8; q++) { h[q] = hist[t * 8 + q]; tot += h[q]; }
        unsigned v = tot;
#pragma unroll
        for (int off = 1; off < 32; off <<= 1) {
            unsigned o = __shfl_down_sync(0xFFFFFFFFu, v, off);
            if (t + off < 32) v += o;
        }
        unsigned nxt = v - tot;
#pragma unroll
        for (int q = 7; q >= 0; q--) {
            unsigned s = nxt + h[q];
            if (s >= KSEL && nxt < KSEL) { sh_cut = (unsigned)(t * 8 + q); sh_above = nxt; }
            nxt = s;
        }
    }
    __syncthreads();                              // [bar 3]

    // writes from register cache
    if (!flagS) {
        const unsigned cut = sh_cut;
        for (int i = 0; i < myn; i++) {
            unsigned ub = c[i].x;
            unsigned bin = (ub >> 16) - 0x4000u;
            bin = (bin > 255u) ? 255u : bin;
            if (bin > cut) {
                orow[c[i].y] = __uint_as_float(ub);       // winner, > 0 (relu identity)
            } else if (bin == cut) {
                unsigned p = atomicAdd(&eq_cnt, 1u);
                if (p < EQCAP) { eq_idx[p] = (int)c[i].y; eq_key[p] = ub; }
                else flagS = 1;
            }
        }
    }
    __syncthreads();                              // [bar 4]

    if (!flagS) {
        const unsigned m = eq_cnt;
        const unsigned need = KSEL - sh_above;
        if (t < (int)m) {
            unsigned u = eq_key[t];
            int idx = eq_idx[t];
            unsigned r = 0;
            for (unsigned j = 0; j < m; j++) {
                unsigned uj = eq_key[j];
                if (uj > u || (uj == u && eq_idx[j] < idx)) r++;
            }
            if (r < need) orow[idx] = __uint_as_float(u);
        }
        return;
    }

    // ===== EXACT FALLBACK (never taken for bench input): radix over the row =====
    unsigned prefix = 0, needv = KSEL;
#pragma unroll 1
    for (int p = 0; p < 4; p++) {
        const int shift = 24 - 8 * p;
        hist[t] = 0u;
        __syncthreads();
        const unsigned hiMask = (p == 0) ? 0u : (0xFFFFFFFFu << (shift + 8));
#pragma unroll 1
        for (int j = t; j < NCOLS; j += TPB2) {
            unsigned k = fkey(xrow[j]);
            if ((k & hiMask) == prefix)
                atomicAdd(&hist[(k >> shift) & 255u], 1u);
        }
        __syncthreads();
        scn[t] = hist[t];
        if (t == 0) scn[256] = 0u;
        __syncthreads();
        for (int off = 1; off < 256; off <<= 1) {
            unsigned a = (t + off < 256) ? scn[t + off] : 0u;
            __syncthreads();
            scn[t] += a;
            __syncthreads();
        }
        if (scn[t] >= needv && (t == 255 ? 0u : scn[t + 1]) < needv) {
            sh_bin = (unsigned)t; sh_need = needv - (t == 255 ? 0u : scn[t + 1]);
        }
        __syncthreads();
        prefix |= sh_bin << shift;
        needv = sh_need;
        __syncthreads();
    }
    const unsigned T = prefix;
    const unsigned need_eq = needv;
    if (t == 0) fb_eqc = 0u;
    __syncthreads();
#pragma unroll 1
    for (int j = t; j < NCOLS; j += TPB2) {
        float f = xrow[j];
        unsigned k = fkey(f);
        if (k > T) {
            orow[j] = fmaxf(f, 0.0f);
        } else if (k == T) {
            unsigned p = atomicAdd(&fb_eqc, 1u);
            if (p < SCAP) fb_list[p] = (unsigned)j;
        }
    }
    __syncthreads();
    if (t == 0) {
        const float tv = fmaxf(keyf(T), 0.0f);
        unsigned n = fb_eqc;
        if (n <= SCAP) {
            int nn = (int)n;
            for (unsigned s = 0; s < need_eq; s++) {
                unsigned best = 0xFFFFFFFFu; int bi = -1;
                for (int i = 0; i < nn; i++) {
                    unsigned idx = fb_list[i];
                    if (idx < best) { best = idx; bi = i; }
                }
                if (bi >= 0) { fb_list[bi] = 0xFFFFFFFFu; orow[best] = tv; }
            }
        } else {
            unsigned w = 0;
            for (int idx = 0; idx < NCOLS && w < need_eq; idx++) {
                if (fkey(xrow[idx]) == T) { orow[idx] = tv; w++; }
            }
        }
    }
}

extern "C" void kernel_launch(void* const* d_in, const int* in_sizes, int n_in,
                              void* d_out, int out_size) {
    const float* x = (const float*)d_in[0];
    float* out = (float*)d_out;
    const int rows = in_sizes[0] / NCOLS;
    k1_stream<<<rows, TPB>>>(x, out);
    k2_select<<<rows, TPB2>>>(x, out);
}

// round 8
// speedup vs baseline: 2.2408x; 2.2408x over previous
#include <cuda_runtime.h>

#define NCOLS 32768
#define TPB   512
#define RPC   4              // rows per CTA
#define F4PT  16             // float4 per thread per row
#define KSEL  32
#define CAP   1280           // per-row candidate capacity (mean 747)
#define EQCAP 64
#define FLOORV 2.0f

__device__ __forceinline__ unsigned fkey(float f) {
    unsigned u = __float_as_uint(f);
    return u ^ ((u >> 31) ? 0xFFFFFFFFu : 0x80000000u);
}
__device__ __forceinline__ float keyf(unsigned k) {
    unsigned u = (k & 0x80000000u) ? (k ^ 0x80000000u) : ~k;
    return __uint_as_float(u);
}

__global__ void __launch_bounds__(TPB, 3)
topk_kernel(const float* __restrict__ x, float* __restrict__ out, int nrows) {
    __shared__ uint2    cand[RPC][CAP];          // 40 KB: (valbits, idx)
    __shared__ unsigned hist[RPC][256];          // 4 KB
    __shared__ unsigned ccnt[RPC];
    __shared__ int      flag[RPC];               // fallback flags
    __shared__ int      vld[RPC];
    __shared__ unsigned eq_cnt[RPC];
    __shared__ int      eq_idx[RPC][EQCAP];
    __shared__ unsigned eq_key[RPC][EQCAP];
    __shared__ unsigned sh_cut[RPC], sh_above[RPC];
    __shared__ unsigned sh_bin, sh_need, fb_eqc;
    __shared__ unsigned scn[257];                // fallback only
    __shared__ unsigned fb_list[256];            // fallback eq idx list (small)

    const int t = threadIdx.x;
    const int rowbase = blockIdx.x * RPC;

    if (t < RPC) {
        ccnt[t] = 0u; flag[t] = 0; eq_cnt[t] = 0u;
        vld[t] = (rowbase + t < nrows) ? 1 : 0;
    }
    // clear 4x256 hists
    hist[t >> 8][t & 255] = 0u;
    hist[(t + TPB) >> 8][t & 255] = 0u;
    __syncthreads();                                          // [bar 1]

    // ===== PHASE 1: stream 4 rows back-to-back (no selection between rows) =====
    const float4 z4 = make_float4(0.f, 0.f, 0.f, 0.f);
#pragma unroll 1
    for (int r = 0; r < RPC; r++) {
        if (!vld[r]) continue;
        const size_t roff = (size_t)(rowbase + r) * NCOLS;
        const float4* __restrict__ xin4 = (const float4*)(x + roff);
        float4* __restrict__ xo4 = (float4*)(out + roff);
#pragma unroll
        for (int jb = 0; jb < F4PT / 4; jb++) {
            float4 v[4];
#pragma unroll
            for (int u = 0; u < 4; u++)                        // 4 back-to-back LDG.128
                v[u] = __ldcs(&xin4[t + (jb * 4 + u) * TPB]);
#pragma unroll
            for (int u = 0; u < 4; u++)                        // 4 back-to-back STG.128
                __stcs(&xo4[t + (jb * 4 + u) * TPB], z4);
#pragma unroll
            for (int u = 0; u < 4; u++) {
                float m = fmaxf(fmaxf(v[u].x, v[u].y), fmaxf(v[u].z, v[u].w));
                if (m >= FLOORV) {                             // rare (~9%)
                    const int base = (t + (jb * 4 + u) * TPB) * 4;
                    const float* fp = (const float*)&v[u];
#pragma unroll
                    for (int c = 0; c < 4; c++) {
                        float f = fp[c];
                        if (f >= FLOORV) {
                            unsigned pos = atomicAdd(&ccnt[r], 1u);   // SHARED atomic
                            if (pos < CAP)
                                cand[r][pos] = make_uint2(__float_as_uint(f),
                                                          (unsigned)(base + c));
                            else flag[r] = 1;
                        }
                    }
                }
            }
        }
    }
    __syncthreads();                                          // [bar 2]

    // ===== PHASE 2: build 4 histograms in parallel =====
#pragma unroll 1
    for (int r = 0; r < RPC; r++) {
        if (flag[r] || !vld[r]) continue;
        const int n = (int)ccnt[r];
        for (int i = t; i < n; i += TPB) {
            unsigned ub = cand[r][i].x;
            unsigned bin = (ub >> 16) - 0x4000u;
            bin = (bin > 255u) ? 255u : bin;
            atomicAdd(&hist[r][bin], 1u);
        }
    }
    __syncthreads();                                          // [bar 3]

    // ===== PHASE 3: warps 0..3 each suffix-scan one row's 256 bins =====
    if (t < 32 * RPC) {
        const int w = t >> 5;                                 // row
        const int lane = t & 31;
        unsigned h[8], tot = 0u;
#pragma unroll
        for (int q = 0; q < 8; q++) { h[q] = hist[w][lane * 8 + q]; tot += h[q]; }
        unsigned v = tot;
#pragma unroll
        for (int off = 1; off < 32; off <<= 1) {
            unsigned o = __shfl_down_sync(0xFFFFFFFFu, v, off);
            if (lane + off < 32) v += o;
        }
        unsigned nxt = v - tot;
#pragma unroll
        for (int q = 7; q >= 0; q--) {
            unsigned s = nxt + h[q];
            if (s >= KSEL && nxt < KSEL) { sh_cut[w] = (unsigned)(lane * 8 + q); sh_above[w] = nxt; }
            nxt = s;
        }
        if (lane == 0 && v < KSEL) flag[w] = 1;               // too few candidates
    }
    __syncthreads();                                          // [bar 4]

    // ===== PHASE 4: writes — 4 groups of 128 threads, one row each =====
    {
        const int r = t >> 7;                                 // group/row
        const int tg = t & 127;
        if (vld[r] && !flag[r]) {
            const unsigned cut = sh_cut[r];
            const int n = (int)ccnt[r];
            for (int i = tg; i < n; i += 128) {
                const unsigned ub = cand[r][i].x;
                const unsigned idx = cand[r][i].y;
                unsigned bin = (ub >> 16) - 0x4000u;
                bin = (bin > 255u) ? 255u : bin;
                if (bin > cut) {
                    out[(size_t)(rowbase + r) * NCOLS + idx] = __uint_as_float(ub);
                } else if (bin == cut) {
                    unsigned p = atomicAdd(&eq_cnt[r], 1u);
                    if (p < EQCAP) { eq_idx[r][p] = (int)idx; eq_key[r][p] = ub; }
                    else flag[r] = 1;
                }
            }
        }
    }
    __syncthreads();                                          // [bar 5]

    // ===== PHASE 5: exact rank inside each cut bin (value desc, index asc) =====
    {
        const int r = t >> 7;
        const int tg = t & 127;
        if (vld[r] && !flag[r]) {
            const unsigned m = eq_cnt[r];
            const unsigned need = KSEL - sh_above[r];
            if (tg < (int)m) {
                unsigned u = eq_key[r][tg];
                int idx = eq_idx[r][tg];
                unsigned rk = 0;
                for (unsigned j = 0; j < m; j++) {
                    unsigned uj = eq_key[r][j];
                    if (uj > u || (uj == u && eq_idx[r][j] < idx)) rk++;
                }
                if (rk < need)
                    out[(size_t)(rowbase + r) * NCOLS + idx] = __uint_as_float(u);
            }
        }
    }
    __syncthreads();                                          // [bar 6]

    // ===== EXACT FALLBACK per flagged row (never taken for bench input) =====
#pragma unroll 1
    for (int r = 0; r < RPC; r++) {
        if (!flag[r] || !vld[r]) continue;                    // uniform (shared flag)
        const size_t roff = (size_t)(rowbase + r) * NCOLS;
        const float* __restrict__ xrow = x + roff;
        float* __restrict__ orow = out + roff;

        unsigned prefix = 0, needv = KSEL;
#pragma unroll 1
        for (int p = 0; p < 4; p++) {
            const int shift = 24 - 8 * p;
            if (t < 256) hist[0][t] = 0u;
            __syncthreads();
            const unsigned hiMask = (p == 0) ? 0u : (0xFFFFFFFFu << (shift + 8));
#pragma unroll 1
            for (int j = t; j < NCOLS; j += TPB) {
                unsigned k = fkey(xrow[j]);
                if ((k & hiMask) == prefix)
                    atomicAdd(&hist[0][(k >> shift) & 255u], 1u);
            }
            __syncthreads();
            if (t < 256) scn[t] = hist[0][t];
            if (t == 0) scn[256] = 0u;
            __syncthreads();
            for (int off = 1; off < 256; off <<= 1) {
                unsigned a = (t < 256 && t + off < 256) ? scn[t + off] : 0u;
                __syncthreads();
                if (t < 256) scn[t] += a;
                __syncthreads();
            }
            if (t < 256) {
                if (scn[t] >= needv && scn[t + 1] < needv) {
                    sh_bin = (unsigned)t; sh_need = needv - scn[t + 1];
                }
            }
            __syncthreads();
            prefix |= sh_bin << shift;
            needv = sh_need;
            __syncthreads();
        }
        const unsigned T = prefix;
        const unsigned need_eq = needv;
        if (t == 0) fb_eqc = 0u;
        __syncthreads();
#pragma unroll 1
        for (int j = t; j < NCOLS; j += TPB) {
            float f = xrow[j];
            unsigned k = fkey(f);
            if (k > T) {
                orow[j] = fmaxf(f, 0.0f);
            } else if (k == T) {
                unsigned p = atomicAdd(&fb_eqc, 1u);
                if (p < 256) fb_list[p] = (unsigned)j;
            }
        }
        __syncthreads();
        if (t == 0) {
            const float tv = fmaxf(keyf(T), 0.0f);
            unsigned n = fb_eqc;
            if (n <= 256) {
                int nn = (int)n;
                for (unsigned s = 0; s < need_eq; s++) {
                    unsigned best = 0xFFFFFFFFu; int bi = -1;
                    for (int i = 0; i < nn; i++) {
                        unsigned idx = fb_list[i];
                        if (idx < best) { best = idx; bi = i; }
                    }
                    if (bi >= 0) { fb_list[bi] = 0xFFFFFFFFu; orow[best] = tv; }
                }
            } else {
                unsigned w = 0;
                for (int idx = 0; idx < NCOLS && w < need_eq; idx++) {
                    if (fkey(xrow[idx]) == T) { orow[idx] = tv; w++; }
                }
            }
        }
        __syncthreads();
    }
}

extern "C" void kernel_launch(void* const* d_in, const int* in_sizes, int n_in,
                              void* d_out, int out_size) {
    const float* x = (const float*)d_in[0];
    float* out = (float*)d_out;
    const int rows = in_sizes[0] / NCOLS;
    const int blocks = (rows + RPC - 1) / RPC;
    topk_kernel<<<blocks, TPB>>>(x, out, rows);
}